// round 15
// baseline (speedup 1.0000x reference)
#include <cuda_runtime.h>
#include <cuda_bf16.h>
#include <cstdint>

#define ALPHA 0.2f

// ---------------- persistent scratch ----------------
__device__ uint4    g_WhT4[5 * 64 * 4096 / 8];   // WhT bf16 [layer][64 cols][4096 nodes]
__device__ float2   g_sq2[5 * 4096];             // (e^s, e^{0.2s})
__device__ float2   g_tq2[5 * 4096];             // (e^t, e^{0.2t})
__device__ unsigned g_adjbits[4096 * 128];       // bit-packed adjacency
__device__ float    g_xres[4096 * 64];
__device__ float    g_part[8 * 4096 * 64];       // partial numerators (8 slots)
__device__ float    g_denp[8 * 4096];            // partial denominators
__device__ unsigned g_wob[64 * 128];             // w_out bf16 transposed [n][k-pairs]

// ---------------- helpers ----------------
__device__ __forceinline__ float elu1(float v) {
    return v > 0.f ? v : (__expf(v) - 1.f);
}
__device__ __forceinline__ void cp16(void* smem_dst, const void* gsrc) {
    unsigned d = (unsigned)__cvta_generic_to_shared(smem_dst);
    asm volatile("cp.async.cg.shared.global [%0], [%1], 16;" :: "r"(d), "l"(gsrc));
}
__device__ __forceinline__ unsigned pkbf(float lo, float hi) {
    unsigned d;
    asm("cvt.rn.bf16x2.f32 %0, %1, %2;" : "=r"(d) : "f"(hi), "f"(lo));
    return d;
}
__device__ __forceinline__ void mma16(float* d, const unsigned* a, unsigned b0, unsigned b1) {
    asm volatile(
        "mma.sync.aligned.m16n8k16.row.col.f32.bf16.bf16.f32 "
        "{%0,%1,%2,%3},{%4,%5,%6,%7},{%8,%9},{%0,%1,%2,%3};"
        : "+f"(d[0]), "+f"(d[1]), "+f"(d[2]), "+f"(d[3])
        : "r"(a[0]), "r"(a[1]), "r"(a[2]), "r"(a[3]), "r"(b0), "r"(b1));
}
#define ONESBF 0x3F803F80u

// ---------------- kA: Wh^T (bf16) + s,t quads + x_residual + adj pack + w_out pack ----------------
// blockIdx.y: 0-3 = heads, 4 = residual, 5 = adjacency bit-pack, 6 = w_out bf16 pack
__global__ __launch_bounds__(256) void kA(const float* __restrict__ x,
                                          const int* __restrict__ adj,
                                          const float* __restrict__ w_heads,
                                          const float* __restrict__ lin_w,
                                          const float* __restrict__ lin_b,
                                          const float* __restrict__ a_heads,
                                          const float* __restrict__ w_out) {
    const int tid = threadIdx.x;
    const int cc = blockIdx.y;

    if (cc == 5) {
        // pack 32 adjacency rows
        const int w = tid >> 5, lane = tid & 31;
        const int row = blockIdx.x * 32 + 4 * w;  // 4 rows per warp
#pragma unroll 4
        for (int rr = 0; rr < 4; rr++) {
            const int* base = adj + (size_t)(row + rr) * 4096;
#pragma unroll 8
            for (int it = 0; it < 128; it++) {
                unsigned m = __ballot_sync(0xffffffffu, base[it * 32 + lane] > 0);
                if (lane == 0) g_adjbits[(row + rr) * 128 + it] = m;
            }
        }
        return;
    }
    if (cc == 6) {
        // pack w_out -> bf16 transposed [n][128 word-pairs]
        if (blockIdx.x < 8) {
            int e = (blockIdx.x * 256 + tid) * 4;  // 4 words per thread
#pragma unroll
            for (int u = 0; u < 4; u++) {
                int n = (e + u) >> 7, kk = (e + u) & 127;
                g_wob[n * 128 + kk] = pkbf(__ldg(w_out + (2 * kk) * 64 + n),
                                           __ldg(w_out + (2 * kk + 1) * 64 + n));
            }
        }
        return;
    }

    __shared__ float xs[32 * 132];
    __shared__ float ws[64 * 68];
    __shared__ float tr[64 * 36];
    const int i0 = blockIdx.x * 32;

#pragma unroll
    for (int u = 0; u < 16; u++) {
        int idx = tid + 256 * u;
        int r = idx >> 7, f = idx & 127;
        xs[r * 132 + f] = x[(i0 + r) * 128 + f];
    }

    const int r = tid >> 3, g = tid & 7;
    float acc[8];
#pragma unroll
    for (int u = 0; u < 8; u++) acc[u] = 0.f;

    for (int fh = 0; fh < 2; fh++) {
        __syncthreads();
        if (cc < 4) {
#pragma unroll
            for (int u = 0; u < 4; u++) {
                int f4 = tid + 256 * u;
                int jj = f4 >> 4, kq = (f4 & 15) * 4;
                *(float4*)&ws[jj * 68 + kq] =
                    *(const float4*)&w_heads[(cc * 128 + fh * 64 + jj) * 64 + kq];
            }
        } else {
#pragma unroll
            for (int u = 0; u < 16; u++) {
                int idx = tid + 256 * u;
                int k = idx >> 6, fo = idx & 63;
                ws[fo * 68 + k] = lin_w[k * 128 + fh * 64 + fo];
            }
        }
        __syncthreads();
#pragma unroll 8
        for (int fo = 0; fo < 64; fo++) {
            float xv = xs[r * 132 + fh * 64 + fo];
            float4 w0 = *(float4*)&ws[fo * 68 + g * 4];
            float4 w1 = *(float4*)&ws[fo * 68 + 32 + g * 4];
            acc[0] += xv * w0.x; acc[1] += xv * w0.y;
            acc[2] += xv * w0.z; acc[3] += xv * w0.w;
            acc[4] += xv * w1.x; acc[5] += xv * w1.y;
            acc[6] += xv * w1.z; acc[7] += xv * w1.w;
        }
    }

    if (cc < 4) {
        const float* av = a_heads + cc * 128;
        float sp = 0.f, tp = 0.f;
#pragma unroll
        for (int u = 0; u < 4; u++) {
            int c0 = g * 4 + u, c1 = 32 + g * 4 + u;
            sp += acc[u] * __ldg(av + c0) + acc[4 + u] * __ldg(av + c1);
            tp += acc[u] * __ldg(av + 64 + c0) + acc[4 + u] * __ldg(av + 64 + c1);
        }
        sp += __shfl_xor_sync(0xffffffffu, sp, 1);
        sp += __shfl_xor_sync(0xffffffffu, sp, 2);
        sp += __shfl_xor_sync(0xffffffffu, sp, 4);
        tp += __shfl_xor_sync(0xffffffffu, tp, 1);
        tp += __shfl_xor_sync(0xffffffffu, tp, 2);
        tp += __shfl_xor_sync(0xffffffffu, tp, 4);
        if (g == 0) {
            g_sq2[cc * 4096 + i0 + r] = make_float2(__expf(sp), __expf(ALPHA * sp));
            g_tq2[cc * 4096 + i0 + r] = make_float2(__expf(tp), __expf(ALPHA * tp));
        }
        // transpose -> bf16 WhT
#pragma unroll
        for (int u = 0; u < 4; u++) {
            tr[(g * 4 + u) * 36 + r] = acc[u];
            tr[(32 + g * 4 + u) * 36 + r] = acc[4 + u];
        }
        __syncthreads();
        {
            int c = tid >> 2, seg = tid & 3;
            float v[8];
#pragma unroll
            for (int q = 0; q < 8; q++) v[q] = tr[c * 36 + seg * 8 + q];
            uint4 pk;
            pk.x = pkbf(v[0], v[1]);
            pk.y = pkbf(v[2], v[3]);
            pk.z = pkbf(v[4], v[5]);
            pk.w = pkbf(v[6], v[7]);
            g_WhT4[(((size_t)(cc * 64 + c)) * 4096 + i0 + seg * 8) >> 3] = pk;
        }
    } else {
        float* dst = g_xres + (size_t)(i0 + r) * 64;
        *(float4*)(dst + g * 4) =
            make_float4(acc[0] + lin_b[g * 4 + 0], acc[1] + lin_b[g * 4 + 1],
                        acc[2] + lin_b[g * 4 + 2], acc[3] + lin_b[g * 4 + 3]);
        *(float4*)(dst + 32 + g * 4) =
            make_float4(acc[4] + lin_b[32 + g * 4 + 0], acc[5] + lin_b[32 + g * 4 + 1],
                        acc[6] + lin_b[32 + g * 4 + 2], acc[7] + lin_b[32 + g * 4 + 3]);
    }
}

// ---------------- kC: fused attention, bf16 m16n8k16, 256 rows/block, j-split ----------------
__global__ __launch_bounds__(256) void kC(int mode) {
    __shared__ __align__(16) __nv_bfloat16 whs[2][64][72];
    __shared__ __align__(16) float2 tst[2][64];

    const int tid = threadIdx.x;
    const int w = tid >> 5, lane = tid & 31;
    const int k = lane & 3, m = lane >> 2;
    const int i0 = blockIdx.x * 256;
    const int y = blockIdx.y;

    int lay, jlo, T;
    if (mode == 0) { lay = y >> 1; jlo = (y & 1) * 2048; T = 32; }
    else           { lay = 4;      jlo = y * 512;        T = 8;  }

    const __nv_bfloat16* WhB = (const __nv_bfloat16*)g_WhT4 + (size_t)lay * 64 * 4096;
    const float2* tq = g_tq2 + lay * 4096;
    const float2* sq = g_sq2 + lay * 4096;

    const int r0 = i0 + 32 * w + m;
    const float2 e0 = sq[r0], e1 = sq[r0 + 8], e2 = sq[r0 + 16], e3 = sq[r0 + 24];
    const unsigned* am0 = g_adjbits + (size_t)r0 * 128 + (jlo >> 5);
    const unsigned* am1 = am0 + 8 * 128;
    const unsigned* am2 = am0 + 16 * 128;
    const unsigned* am3 = am0 + 24 * 128;

    float accA[9][4], accB[9][4];
#pragma unroll
    for (int n = 0; n < 9; n++)
#pragma unroll
        for (int u = 0; u < 4; u++) { accA[n][u] = 0.f; accB[n][u] = 0.f; }

#pragma unroll
    for (int u = 0; u < 2; u++) {
        int idx = tid + 256 * u;
        int c = idx >> 3, ch = idx & 7;
        cp16(&whs[0][c][ch * 8], WhB + (size_t)c * 4096 + jlo + ch * 8);
    }
    if (tid < 32) cp16(&tst[0][tid * 2], tq + jlo + tid * 2);
    asm volatile("cp.async.commit_group;");
    uint2 M0 = *(const uint2*)am0;
    uint2 M1 = *(const uint2*)am1;
    uint2 M2 = *(const uint2*)am2;
    uint2 M3 = *(const uint2*)am3;
    asm volatile("cp.async.wait_group 0;" ::: "memory");
    __syncthreads();

    for (int t = 0; t < T; t++) {
        const int b = t & 1, nb = b ^ 1;

        uint2 N0, N1, N2, N3;
        if (t + 1 < T) {
            const int j0n = jlo + (t + 1) * 64;
#pragma unroll
            for (int u = 0; u < 2; u++) {
                int idx = tid + 256 * u;
                int c = idx >> 3, ch = idx & 7;
                cp16(&whs[nb][c][ch * 8], WhB + (size_t)c * 4096 + j0n + ch * 8);
            }
            if (tid < 32) cp16(&tst[nb][tid * 2], tq + j0n + tid * 2);
            asm volatile("cp.async.commit_group;");
            N0 = *(const uint2*)(am0 + 2 * (t + 1));
            N1 = *(const uint2*)(am1 + 2 * (t + 1));
            N2 = *(const uint2*)(am2 + 2 * (t + 1));
            N3 = *(const uint2*)(am3 + 2 * (t + 1));
        }

#pragma unroll
        for (int s = 0; s < 4; s++) {
            const float4 tA = *(const float4*)&tst[b][16 * s + 2 * k];
            const float4 tB = *(const float4*)&tst[b][16 * s + 2 * k + 8];
            const int sh = (s & 1) * 16 + 2 * k;
            const unsigned h0 = ((s >= 2) ? M0.y : M0.x) >> sh;
            const unsigned h1 = ((s >= 2) ? M1.y : M1.x) >> sh;
            const unsigned h2 = ((s >= 2) ? M2.y : M2.x) >> sh;
            const unsigned h3 = ((s >= 2) ? M3.y : M3.x) >> sh;

            unsigned afrA[4], afrB[4];
            {
                float p0 = (h0 & 1u) ? fmaxf(e0.x * tA.x, e0.y * tA.y) : 0.f;
                float p1 = ((h0 >> 1) & 1u) ? fmaxf(e0.x * tA.z, e0.y * tA.w) : 0.f;
                float p8 = ((h0 >> 8) & 1u) ? fmaxf(e0.x * tB.x, e0.y * tB.y) : 0.f;
                float p9 = ((h0 >> 9) & 1u) ? fmaxf(e0.x * tB.z, e0.y * tB.w) : 0.f;
                afrA[0] = pkbf(p0, p1); afrA[2] = pkbf(p8, p9);
            }
            {
                float p0 = (h1 & 1u) ? fmaxf(e1.x * tA.x, e1.y * tA.y) : 0.f;
                float p1 = ((h1 >> 1) & 1u) ? fmaxf(e1.x * tA.z, e1.y * tA.w) : 0.f;
                float p8 = ((h1 >> 8) & 1u) ? fmaxf(e1.x * tB.x, e1.y * tB.y) : 0.f;
                float p9 = ((h1 >> 9) & 1u) ? fmaxf(e1.x * tB.z, e1.y * tB.w) : 0.f;
                afrA[1] = pkbf(p0, p1); afrA[3] = pkbf(p8, p9);
            }
            {
                float p0 = (h2 & 1u) ? fmaxf(e2.x * tA.x, e2.y * tA.y) : 0.f;
                float p1 = ((h2 >> 1) & 1u) ? fmaxf(e2.x * tA.z, e2.y * tA.w) : 0.f;
                float p8 = ((h2 >> 8) & 1u) ? fmaxf(e2.x * tB.x, e2.y * tB.y) : 0.f;
                float p9 = ((h2 >> 9) & 1u) ? fmaxf(e2.x * tB.z, e2.y * tB.w) : 0.f;
                afrB[0] = pkbf(p0, p1); afrB[2] = pkbf(p8, p9);
            }
            {
                float p0 = (h3 & 1u) ? fmaxf(e3.x * tA.x, e3.y * tA.y) : 0.f;
                float p1 = ((h3 >> 1) & 1u) ? fmaxf(e3.x * tA.z, e3.y * tA.w) : 0.f;
                float p8 = ((h3 >> 8) & 1u) ? fmaxf(e3.x * tB.x, e3.y * tB.y) : 0.f;
                float p9 = ((h3 >> 9) & 1u) ? fmaxf(e3.x * tB.z, e3.y * tB.w) : 0.f;
                afrB[1] = pkbf(p0, p1); afrB[3] = pkbf(p8, p9);
            }

#pragma unroll
            for (int n = 0; n < 8; n++) {
                const __nv_bfloat16* bp = &whs[b][8 * n + m][16 * s + 2 * k];
                unsigned b0 = *(const unsigned*)bp;
                unsigned b1 = *(const unsigned*)(bp + 8);
                mma16(accA[n], afrA, b0, b1);
                mma16(accB[n], afrB, b0, b1);
            }
            mma16(accA[8], afrA, ONESBF, ONESBF);
            mma16(accB[8], afrB, ONESBF, ONESBF);
        }

        if (t + 1 < T) {
            asm volatile("cp.async.wait_group 0;" ::: "memory");
            M0 = N0; M1 = N1; M2 = N2; M3 = N3;
        }
        __syncthreads();
    }

    const int slot = y;
    float* p0 = g_part + ((size_t)slot * 4096 + r0) * 64 + 2 * k;
    float* p1 = p0 + 8 * 64;
    float* p2 = p0 + 16 * 64;
    float* p3 = p0 + 24 * 64;
#pragma unroll
    for (int n = 0; n < 8; n++) {
        *(float2*)(p0 + 8 * n) = make_float2(accA[n][0], accA[n][1]);
        *(float2*)(p1 + 8 * n) = make_float2(accA[n][2], accA[n][3]);
        *(float2*)(p2 + 8 * n) = make_float2(accB[n][0], accB[n][1]);
        *(float2*)(p3 + 8 * n) = make_float2(accB[n][2], accB[n][3]);
    }
    if (k == 0) {
        g_denp[slot * 4096 + r0] = accA[8][0];
        g_denp[slot * 4096 + r0 + 8] = accA[8][2];
        g_denp[slot * 4096 + r0 + 16] = accB[8][0];
        g_denp[slot * 4096 + r0 + 24] = accB[8][2];
    }
}

// ---------------- kE: combine heads + out GEMM (bf16 mma) + quads + WhT ----------------
// smem (bytes): wbw [64][132] words @0 (33792), hcw [32][132] words @33792 (16896),
//               whs [32][68] f32 @50688 (8704), dhs [32][4] f32 @59392 (512)
#define KE_SMEM 59904
extern __shared__ char smE[];
__global__ __launch_bounds__(256) void kE(const float* __restrict__ a_out) {
    unsigned* wbw = (unsigned*)smE;
    unsigned* hcw = (unsigned*)(smE + 33792);
    float* whs = (float*)(smE + 50688);
    float* dhs = (float*)(smE + 59392);
    const int tid = threadIdx.x;
    const int i0 = blockIdx.x * 32;

    if (tid < 128) {
        int r = tid >> 2, h = tid & 3, row = i0 + r;
        dhs[r * 4 + h] =
            1.f / (g_denp[(2 * h) * 4096 + row] + g_denp[(2 * h + 1) * 4096 + row]);
    }
    // stage prepacked w_out via cp.async
#pragma unroll
    for (int u = 0; u < 8; u++) {
        int gg = tid + 256 * u;          // 2048 groups of 4 words
        int n = gg >> 5, k4 = (gg & 31) * 4;
        cp16(&wbw[n * 132 + k4], &g_wob[n * 128 + k4]);
    }
    asm volatile("cp.async.commit_group;");
    __syncthreads();   // dhs visible

    // combine head partials -> hc bf16 [m][k], float4 loads
#pragma unroll
    for (int u = 0; u < 8; u++) {
        int e = tid + 256 * u;           // 2048 = 32 rows x 64 quads
        int m = e >> 6, q = e & 63;
        int h = q >> 4, c = (q & 15) * 4;
        int row = i0 + m;
        const float* pa = g_part + ((size_t)(2 * h) * 4096 + row) * 64 + c;
        float4 va = *(const float4*)pa;
        float4 vb = *(const float4*)(pa + 4096 * 64);
        float di = dhs[m * 4 + h];
        uint2 o;
        o.x = pkbf(elu1((va.x + vb.x) * di), elu1((va.y + vb.y) * di));
        o.y = pkbf(elu1((va.z + vb.z) * di), elu1((va.w + vb.w) * di));
        *(uint2*)&hcw[m * 132 + 2 * q] = o;
    }
    asm volatile("cp.async.wait_group 0;" ::: "memory");
    __syncthreads();

    // GEMM: warp = (mblk, nquad)
    const int wid = tid >> 5, lane = tid & 31;
    const int mblk = wid & 1, nq = wid >> 1;
    const int mrow = 16 * mblk + (lane >> 2), kq = lane & 3;
    float acc[2][4];
#pragma unroll
    for (int ni = 0; ni < 2; ni++)
#pragma unroll
        for (int u = 0; u < 4; u++) acc[ni][u] = 0.f;

#pragma unroll
    for (int ks = 0; ks < 16; ks++) {
        unsigned A[4];
        A[0] = hcw[mrow * 132 + 8 * ks + kq];
        A[1] = hcw[(mrow + 8) * 132 + 8 * ks + kq];
        A[2] = hcw[mrow * 132 + 8 * ks + kq + 4];
        A[3] = hcw[(mrow + 8) * 132 + 8 * ks + kq + 4];
#pragma unroll
        for (int ni = 0; ni < 2; ni++) {
            int n = 2 * nq + ni;
            unsigned b0 = wbw[(8 * n + (lane >> 2)) * 132 + 8 * ks + kq];
            unsigned b1 = wbw[(8 * n + (lane >> 2)) * 132 + 8 * ks + kq + 4];
            mma16(acc[ni], A, b0, b1);
        }
    }

#pragma unroll
    for (int ni = 0; ni < 2; ni++) {
        int col = 8 * (2 * nq + ni) + 2 * kq;
        *(float2*)&whs[mrow * 68 + col] = make_float2(acc[ni][0], acc[ni][1]);
        *(float2*)&whs[(mrow + 8) * 68 + col] = make_float2(acc[ni][2], acc[ni][3]);
    }
    __syncthreads();

    // layer-4 s,t quads
    {
        const int r = tid >> 3, g = tid & 7;
        float sp = 0.f, tp = 0.f;
#pragma unroll
        for (int u = 0; u < 8; u++) {
            int c = g * 8 + u;
            float v = whs[r * 68 + c];
            sp += v * __ldg(a_out + c);
            tp += v * __ldg(a_out + 64 + c);
        }
        sp += __shfl_xor_sync(0xffffffffu, sp, 1);
        sp += __shfl_xor_sync(0xffffffffu, sp, 2);
        sp += __shfl_xor_sync(0xffffffffu, sp, 4);
        tp += __shfl_xor_sync(0xffffffffu, tp, 1);
        tp += __shfl_xor_sync(0xffffffffu, tp, 2);
        tp += __shfl_xor_sync(0xffffffffu, tp, 4);
        if (g == 0) {
            g_sq2[4 * 4096 + i0 + r] = make_float2(__expf(sp), __expf(ALPHA * sp));
            g_tq2[4 * 4096 + i0 + r] = make_float2(__expf(tp), __expf(ALPHA * tp));
        }
    }

    // transposed bf16 WhT store
    {
        int col = tid >> 2, seg = tid & 3;
        float v[8];
#pragma unroll
        for (int q = 0; q < 8; q++) v[q] = whs[(seg * 8 + q) * 68 + col];
        uint4 pk;
        pk.x = pkbf(v[0], v[1]);
        pk.y = pkbf(v[2], v[3]);
        pk.z = pkbf(v[4], v[5]);
        pk.w = pkbf(v[6], v[7]);
        g_WhT4[(((size_t)(4 * 64 + col)) * 4096 + i0 + seg * 8) >> 3] = pk;
    }
}

// ---------------- kG: combine out-layer partials + residual + final linear + elu ----------------
__global__ __launch_bounds__(256) void kG(const float* __restrict__ outlin_w,
                                          const float* __restrict__ outlin_b,
                                          float* __restrict__ out) {
    __shared__ float vi[32 * 68];
    __shared__ float wt[64 * 68];
    __shared__ float dinv[32];
    const int tid = threadIdx.x;
    const int i0 = blockIdx.x * 32;

    if (tid < 32) {
        int row = i0 + tid;
        float ds = 0.f;
#pragma unroll
        for (int s = 0; s < 8; s++) ds += g_denp[s * 4096 + row];
        dinv[tid] = 1.f / ds;
    }
#pragma unroll
    for (int u = 0; u < 16; u++) {
        int idx = tid + 256 * u;
        int k2 = idx >> 6, k = idx & 63;
        wt[k * 68 + k2] = outlin_w[k2 * 64 + k];
    }
    __syncthreads();

#pragma unroll
    for (int u = 0; u < 2; u++) {
        int idx = tid + 256 * u;
        int r = idx >> 4, kq = (idx & 15) * 4;
        int row = i0 + r;
        float4 n = make_float4(0.f, 0.f, 0.f, 0.f);
#pragma unroll
        for (int s = 0; s < 8; s++) {
            float4 v = *(const float4*)&g_part[((size_t)s * 4096 + row) * 64 + kq];
            n.x += v.x; n.y += v.y; n.z += v.z; n.w += v.w;
        }
        float4 xa = *(const float4*)&g_xres[(size_t)row * 64 + kq];
        float di = dinv[r];
        xa.x += elu1(n.x * di);
        xa.y += elu1(n.y * di);
        xa.z += elu1(n.z * di);
        xa.w += elu1(n.w * di);
        *(float4*)&vi[r * 68 + kq] = xa;
    }
    __syncthreads();

    const int r = tid >> 3, g = tid & 7;
    float acc[8];
#pragma unroll
    for (int u = 0; u < 8; u++) acc[u] = 0.f;
#pragma unroll 8
    for (int k = 0; k < 64; k++) {
        float xv = vi[r * 68 + k];
        float4 w0 = *(float4*)&wt[k * 68 + g * 4];
        float4 w1 = *(float4*)&wt[k * 68 + 32 + g * 4];
        acc[0] += xv * w0.x; acc[1] += xv * w0.y;
        acc[2] += xv * w0.z; acc[3] += xv * w0.w;
        acc[4] += xv * w1.x; acc[5] += xv * w1.y;
        acc[6] += xv * w1.z; acc[7] += xv * w1.w;
    }
    float* dst = out + (size_t)(i0 + r) * 64;
    *(float4*)(dst + g * 4) = make_float4(
        elu1(acc[0] + outlin_b[g * 4 + 0]), elu1(acc[1] + outlin_b[g * 4 + 1]),
        elu1(acc[2] + outlin_b[g * 4 + 2]), elu1(acc[3] + outlin_b[g * 4 + 3]));
    *(float4*)(dst + 32 + g * 4) = make_float4(
        elu1(acc[4] + outlin_b[32 + g * 4 + 0]), elu1(acc[5] + outlin_b[32 + g * 4 + 1]),
        elu1(acc[6] + outlin_b[32 + g * 4 + 2]), elu1(acc[7] + outlin_b[32 + g * 4 + 3]));
}

// ---------------- launch ----------------
extern "C" void kernel_launch(void* const* d_in, const int* in_sizes, int n_in,
                              void* d_out, int out_size) {
    const float* x        = (const float*)d_in[0];
    const int*   adj      = (const int*)d_in[1];
    const float* w_heads  = (const float*)d_in[2];
    const float* a_heads  = (const float*)d_in[3];
    const float* w_out    = (const float*)d_in[4];
    const float* a_out    = (const float*)d_in[5];
    const float* lin_w    = (const float*)d_in[6];
    const float* lin_b    = (const float*)d_in[7];
    const float* outlin_w = (const float*)d_in[8];
    const float* outlin_b = (const float*)d_in[9];
    float* out = (float*)d_out;

    static int inited = 0;
    if (!inited) {
        cudaFuncSetAttribute(kE, cudaFuncAttributeMaxDynamicSharedMemorySize, KE_SMEM);
        inited = 1;
    }

    kA<<<dim3(128, 7), 256>>>(x, adj, w_heads, lin_w, lin_b, a_heads, w_out);
    kC<<<dim3(16, 8), 256>>>(0);           // 4 heads x 2 j-slices -> partials
    kE<<<128, 256, KE_SMEM>>>(a_out);      // combine + out GEMM + quads + WhT
    kC<<<dim3(16, 8), 256>>>(1);           // out layer, 8 j-slices -> partials
    kG<<<128, 256>>>(outlin_w, outlin_b, out);
}